// round 7
// baseline (speedup 1.0000x reference)
#include <cuda_runtime.h>
#include <math.h>
#include <float.h>

// Problem constants (from reference setup_inputs)
#define BB 16
#define KK 32768
#define NN 64
#define CC 21
#define RPB 128                          // threads per block (4 warps)
#define NW  (RPB / 32)
#define TROWS 256                        // rows per tile
#define RPT 2                            // rows per thread per tile
#define TPB 4                            // tiles per block (contiguous)
#define NTILES ((BB * KK) / TROWS)       // 2048
#define GRIDB (NTILES / TPB)             // 512 blocks
#define CONF_V4 ((TROWS * CC) / 4)       // 1344 float4 per tile
#define EPSF 1.1920929e-07f

__device__ float g_pl[GRIDB];
__device__ float g_pc[GRIDB];
__device__ int   g_pp[GRIDB];
__device__ unsigned int g_ticket = 0;    // self-resetting via atomicInc wrap

__device__ __forceinline__ void stage_conf(float* sbuf, const float* gsrc) {
    unsigned int sa = (unsigned int)__cvta_generic_to_shared(sbuf);
    const float4* g = (const float4*)gsrc;
    for (int i = threadIdx.x; i < CONF_V4; i += RPB) {
        asm volatile("cp.async.cg.shared.global [%0], [%1], 16;\n"
                     :: "r"(sa + (unsigned)i * 16u), "l"(g + i));
    }
}
#define CP_COMMIT()  asm volatile("cp.async.commit_group;\n")
#define CP_WAIT1()   asm volatile("cp.async.wait_group 1;\n")

__global__ __launch_bounds__(RPB) void msl_kernel(
    const float* __restrict__ loc_data,   // (B,K,2)
    const float* __restrict__ conf_data,  // (B,K,C)
    const float* __restrict__ priors,     // (K,2)
    const float* __restrict__ truths,     // (B,N,2)
    const int*   __restrict__ labels_raw, // (B,N) int32 or int64 (auto-detect)
    const int*   __restrict__ clip_raw,   // scalar (int/float bits) or null
    float* __restrict__ out)
{
    __shared__ float  s_conf[2][TROWS * CC];   // 43008 B double buffer
    __shared__ float2 s_tru[NN];               // raw truths for this batch
    __shared__ int    s_lraw[NN];
    __shared__ float4 s_cseg[NN];              // compacted {t0, t1, len*cl, _}
    __shared__ int    s_clab[NN];
    __shared__ float  s_wmin[NW], s_wmax[NW];
    __shared__ int    s_m;
    __shared__ float  s_red_l[NW];
    __shared__ float  s_red_c[NW];
    __shared__ int    s_red_p[NW];
    __shared__ int    s_islast;

    const int tid = threadIdx.x;
    const int warp = tid >> 5;
    const int lane = tid & 31;
    const int t0 = blockIdx.x * TPB;           // first tile of this block
    const int b = t0 / (KK / TROWS);           // all TPB tiles share one batch
    const int kbase0 = t0 * TROWS - b * KK;    // k of first row of tile 0

    // clip_length: handle int32 / int64-low-word / float32 encodings
    float cl = 256.0f;
    if (clip_raw) {
        int vi = clip_raw[0];
        float vf = __int_as_float(vi);
        cl = (vi > 0 && vi <= (1 << 20)) ? (float)vi : vf;
    }
    const float maxn = 2.0f * cl;

    // Load truths + labels once for the block's batch
    if (tid < NN) {
        s_tru[tid] = ((const float2*)truths)[b * NN + tid];
        bool is64 = (labels_raw[1] == 0);      // labels >= 1 always
        s_lraw[tid] = is64 ? labels_raw[2 * (b * NN + tid)]
                           : labels_raw[b * NN + tid];
    }

    // Prologue: stage conf tiles 0 and 1 (async), prefetch tile 0 scalars
    stage_conf(s_conf[0], conf_data + (size_t)t0 * TROWS * CC);
    CP_COMMIT();
    stage_conf(s_conf[1], conf_data + (size_t)(t0 + 1) * TROWS * CC);
    CP_COMMIT();

    int kA = kbase0 + tid;
    float  cenA = __ldg(&priors[2 * kA]);
    float  cenB = __ldg(&priors[2 * (kA + RPB)]);
    float2 locA = ((const float2*)loc_data)[b * KK + kA];
    float2 locB = ((const float2*)loc_data)[b * KK + kA + RPB];

    float accL = 0.0f, accC = 0.0f;
    int   accP = 0;

    #pragma unroll
    for (int j = 0; j < TPB; j++) {
        CP_WAIT1();              // conf tile j resident (this thread's groups)
        __syncthreads();         // all threads' groups + truths (j==0) visible

        // ---- per-tile min/max of centers ----
        float mn = fminf(cenA, cenB), mx = fmaxf(cenA, cenB);
        #pragma unroll
        for (int o = 16; o > 0; o >>= 1) {
            mn = fminf(mn, __shfl_xor_sync(0xffffffffu, mn, o));
            mx = fmaxf(mx, __shfl_xor_sync(0xffffffffu, mx, o));
        }
        if (lane == 0) { s_wmin[warp] = mn; s_wmax[warp] = mx; }
        __syncthreads();

        // ---- warp 0: compact segments intersecting [lo, hi] ----
        if (warp == 0) {
            float lo = s_wmin[0], hi = s_wmax[0];
            #pragma unroll
            for (int w = 1; w < NW; w++) {
                lo = fminf(lo, s_wmin[w]);
                hi = fmaxf(hi, s_wmax[w]);
            }
            float2 tA = s_tru[lane];
            float2 tB = s_tru[lane + 32];
            bool vA = (tA.y >= lo) && (tA.x <= hi);
            bool vB = (tB.y >= lo) && (tB.x <= hi);
            unsigned bA = __ballot_sync(0xffffffffu, vA);
            unsigned bBv = __ballot_sync(0xffffffffu, vB);
            unsigned ltm = (1u << lane) - 1u;
            int cntA = __popc(bA);
            if (vA) {
                int p = __popc(bA & ltm);
                s_cseg[p] = make_float4(tA.x, tA.y, (tA.y - tA.x) * cl, 0.0f);
                s_clab[p] = s_lraw[lane];
            }
            if (vB) {
                int p = cntA + __popc(bBv & ltm);
                s_cseg[p] = make_float4(tB.x, tB.y, (tB.y - tB.x) * cl, 0.0f);
                s_clab[p] = s_lraw[lane + 32];
            }
            if (lane == 0) s_m = cntA + __popc(bBv);
        }
        __syncthreads();

        // ---- prefetch next tile's scalars (latency hidden under compute) ----
        float  cenA_n = 0.0f, cenB_n = 0.0f;
        float2 locA_n = make_float2(0.0f, 0.0f);
        float2 locB_n = make_float2(0.0f, 0.0f);
        if (j + 1 < TPB) {
            int kN = kbase0 + (j + 1) * TROWS + tid;
            cenA_n = __ldg(&priors[2 * kN]);
            cenB_n = __ldg(&priors[2 * (kN + RPB)]);
            locA_n = ((const float2*)loc_data)[b * KK + kN];
            locB_n = ((const float2*)loc_data)[b * KK + kN + RPB];
        }

        // ---- argmin over m candidates, both rows ----
        const int m = s_m;
        float bestA = maxn, bestB = maxn;
        int bnA = 0, bnB = 0;
        #pragma unroll 4
        for (int n = 0; n < m; n++) {
            float4 sg = s_cseg[n];
            bool okA = (cenA >= sg.x) && (cenA <= sg.y);
            bool okB = (cenB >= sg.x) && (cenB <= sg.y);
            float cAv = okA ? sg.z : maxn;
            float cBv = okB ? sg.z : maxn;
            if (cAv < bestA) { bestA = cAv; bnA = n; }
            if (cBv < bestB) { bestB = cBv; bnB = n; }
        }

        int confA = 0, confB = 0;
        if (m > 0) {
            const float4 bsA = s_cseg[bnA];
            const float4 bsB = s_cseg[bnB];
            confA = (bestA >= maxn) ? 0 : s_clab[bnA];
            confB = (bestB >= maxn) ? 0 : s_clab[bnB];
            if (confA > 0) {
                float tl = (cenA - bsA.x) * cl;
                float tr = (bsA.y - cenA) * cl;
                float inter = fminf(locA.x, tl) + fminf(locA.y, tr);
                float uni = (locA.x + locA.y) + (tl + tr) - inter;
                float ious = __fdividef(inter, fmaxf(uni, EPSF));
                float ac = fmaxf(locA.x, tl) + fmaxf(locA.y, tr);
                accL += 1.0f - (ious - __fdividef(ac - uni, fmaxf(ac, EPSF)));
            }
            if (confB > 0) {
                float tl = (cenB - bsB.x) * cl;
                float tr = (bsB.y - cenB) * cl;
                float inter = fminf(locB.x, tl) + fminf(locB.y, tr);
                float uni = (locB.x + locB.y) + (tl + tr) - inter;
                float ious = __fdividef(inter, fmaxf(uni, EPSF));
                float ac = fmaxf(locB.x, tl) + fmaxf(locB.y, tr);
                accL += 1.0f - (ious - __fdividef(ac - uni, fmaxf(ac, EPSF)));
            }
        }
        accP += (confA > 0) + (confB > 0);

        // ---- focal loss: interleaved softmax sums + target gather ----
        const float* crowA = s_conf[j & 1] + tid * CC;
        const float* crowB = s_conf[j & 1] + (tid + RPB) * CC;
        float sumA = 0.0f, sumB = 0.0f;
        #pragma unroll
        for (int c = 0; c < CC; c++) {
            sumA += __expf(crowA[c]);
            sumB += __expf(crowB[c]);
        }
        float etA = __expf(crowA[confA]);
        float etB = __expf(crowB[confB]);
        float ptA = __fdividef(etA, sumA) + 1e-6f;
        float ptB = __fdividef(etB, sumB) + 1e-6f;
        float aA = (confA == 0) ? 0.25f : 0.75f;
        float aB = (confB == 0) ? 0.25f : 0.75f;
        float omA = 1.0f - ptA;
        float omB = 1.0f - ptB;
        accC += -omA * omA * aA * __logf(ptA) - omB * omB * aB * __logf(ptB);

        __syncthreads();         // everyone done reading s_conf[j&1]

        // ---- restage buffer j&1 with tile j+2 (or empty group) ----
        if (j + 2 < TPB)
            stage_conf(s_conf[j & 1],
                       conf_data + (size_t)(t0 + j + 2) * TROWS * CC);
        CP_COMMIT();             // exactly one group per iteration

        cenA = cenA_n; cenB = cenB_n;
        locA = locA_n; locB = locB_n;
    }

    // ---- block reduction of accumulators ----
    float v0 = accL, v1 = accC;
    int vp = accP;
    #pragma unroll
    for (int o = 16; o > 0; o >>= 1) {
        v0 += __shfl_down_sync(0xffffffffu, v0, o);
        v1 += __shfl_down_sync(0xffffffffu, v1, o);
        vp += __shfl_down_sync(0xffffffffu, vp, o);
    }
    if (lane == 0) {
        s_red_l[warp] = v0;
        s_red_c[warp] = v1;
        s_red_p[warp] = vp;
    }
    __syncthreads();
    if (tid == 0) {
        float r0 = 0.0f, r1 = 0.0f;
        int rp = 0;
        #pragma unroll
        for (int w = 0; w < NW; w++) { r0 += s_red_l[w]; r1 += s_red_c[w]; rp += s_red_p[w]; }
        g_pl[blockIdx.x] = r0;
        g_pc[blockIdx.x] = r1;
        g_pp[blockIdx.x] = rp;
        __threadfence();
        unsigned int old = atomicInc(&g_ticket, GRIDB - 1);  // wraps: replay-safe
        s_islast = (old == GRIDB - 1);
    }
    __syncthreads();

    // ---- last block: final reduction over all partials ----
    if (s_islast) {
        float f0 = 0.0f, f1 = 0.0f;
        int fp = 0;
        #pragma unroll
        for (int i = tid; i < GRIDB; i += RPB) {
            f0 += *(volatile float*)&g_pl[i];
            f1 += *(volatile float*)&g_pc[i];
            fp += *(volatile int*)&g_pp[i];
        }
        #pragma unroll
        for (int o = 16; o > 0; o >>= 1) {
            f0 += __shfl_down_sync(0xffffffffu, f0, o);
            f1 += __shfl_down_sync(0xffffffffu, f1, o);
            fp += __shfl_down_sync(0xffffffffu, fp, o);
        }
        if (lane == 0) {
            s_red_l[warp] = f0;
            s_red_c[warp] = f1;
            s_red_p[warp] = fp;
        }
        __syncthreads();
        if (tid == 0) {
            float r0 = 0.0f, r1 = 0.0f;
            int rp = 0;
            #pragma unroll
            for (int w = 0; w < NW; w++) { r0 += s_red_l[w]; r1 += s_red_c[w]; rp += s_red_p[w]; }
            float np = (rp > 0) ? (float)rp : 1.0f;
            out[0] = r0 / np;
            out[1] = r1 / np;
        }
    }
}

extern "C" void kernel_launch(void* const* d_in, const int* in_sizes, int n_in,
                              void* d_out, int out_size) {
    const float* loc_data  = (const float*)d_in[0];
    const float* conf_data = (const float*)d_in[1];
    const float* priors    = (const float*)d_in[2];
    const float* truths    = (const float*)d_in[3];
    const int*   labels    = (const int*)d_in[4];
    const int*   clip      = (n_in >= 6) ? (const int*)d_in[5] : nullptr;

    msl_kernel<<<GRIDB, RPB>>>(loc_data, conf_data, priors, truths, labels,
                               clip, (float*)d_out);
}

// round 8
// speedup vs baseline: 1.1248x; 1.1248x over previous
#include <cuda_runtime.h>
#include <math.h>
#include <float.h>

// Problem constants (from reference setup_inputs)
#define BB 16
#define KK 32768
#define NN 64
#define CC 21
#define RPB 128                         // threads per block (4 warps)
#define NW  (RPB / 32)
#define ROWS 256                        // rows per block (64 per warp)
#define GRID ((BB * KK) / ROWS)         // 2048 blocks
#define WCONF (64 * CC)                 // floats per warp conf region (1344)
#define WV4   (WCONF / 4)               // 336 float4 per warp region
#define EPSF 1.1920929e-07f

__device__ float g_pl[GRID];
__device__ float g_pc[GRID];
__device__ int   g_pp[GRID];
__device__ unsigned int g_ticket = 0;   // self-resetting via atomicInc wrap

__global__ __launch_bounds__(RPB) void msl_kernel(
    const float* __restrict__ loc_data,   // (B,K,2)
    const float* __restrict__ conf_data,  // (B,K,C)
    const float* __restrict__ priors,     // (K,2)
    const float* __restrict__ truths,     // (B,N,2)
    const int*   __restrict__ labels_raw, // (B,N) int32 or int64 (auto-detect)
    const int*   __restrict__ clip_raw,   // scalar (int/float bits) or null
    float* __restrict__ out)
{
    __shared__ float  s_conf[ROWS * CC];     // 21504 B, warp w owns [w*1344, +1344)
    __shared__ float4 s_cseg[NW * NN];       // per-warp compacted {t0,t1,len*cl,label}
    __shared__ float  s_red_l[NW];
    __shared__ float  s_red_c[NW];
    __shared__ int    s_red_p[NW];
    __shared__ int    s_islast;

    const int tid  = threadIdx.x;
    const int warp = tid >> 5;
    const int lane = tid & 31;
    const int row0 = blockIdx.x * ROWS;
    const int b = row0 / KK;                 // whole block within one batch
    // warp-contiguous row assignment: warp owns rows [warp*64, warp*64+64)
    const int lrowA = warp * 64 + lane;      // local row A
    const int rowA  = row0 + lrowA;
    const int rowB  = rowA + 32;
    const int kA    = rowA - b * KK;

    // clip_length: handle int32 / int64-low-word / float32 encodings
    float cl = 256.0f;
    if (clip_raw) {
        int vi = clip_raw[0];
        float vf = __int_as_float(vi);
        cl = (vi > 0 && vi <= (1 << 20)) ? (float)vi : vf;
    }
    const float maxn = 2.0f * cl;

    // ---- warp stages ITS OWN 64-row conf slice (float4, coalesced) ----
    {
        const float4* src = (const float4*)(conf_data
                              + (size_t)(row0 + warp * 64) * CC);
        float4* dst = (float4*)(s_conf + warp * WCONF);
        #pragma unroll
        for (int i = lane; i < WV4; i += 32)
            dst[i] = src[i];
    }

    // ---- scalar loads (issue while staging loads are in flight) ----
    const float cenA = __ldg(&priors[2 * kA]);
    const float cenB = __ldg(&priors[2 * (kA + 32)]);
    const float2 pA = ((const float2*)loc_data)[rowA];
    const float2 pB = ((const float2*)loc_data)[rowB];
    const float2 tA = ((const float2*)truths)[b * NN + lane];
    const float2 tB = ((const float2*)truths)[b * NN + lane + 32];
    const bool is64 = (__ldg(&labels_raw[1]) == 0);  // labels >= 1 always
    const int labA = is64 ? __ldg(&labels_raw[2 * (b * NN + lane)])
                          : __ldg(&labels_raw[b * NN + lane]);
    const int labB = is64 ? __ldg(&labels_raw[2 * (b * NN + lane + 32)])
                          : __ldg(&labels_raw[b * NN + lane + 32]);

    // ---- warp min/max of its 64 centers ----
    float mn = fminf(cenA, cenB), mx = fmaxf(cenA, cenB);
    #pragma unroll
    for (int o = 16; o > 0; o >>= 1) {
        mn = fminf(mn, __shfl_xor_sync(0xffffffffu, mn, o));
        mx = fmaxf(mx, __shfl_xor_sync(0xffffffffu, mx, o));
    }
    // mn/mx now uniform across the warp

    // ---- warp-local segment compaction (order-preserving) ----
    const bool vA = (tA.y >= mn) && (tA.x <= mx);
    const bool vB = (tB.y >= mn) && (tB.x <= mx);
    const unsigned bA  = __ballot_sync(0xffffffffu, vA);
    const unsigned bBv = __ballot_sync(0xffffffffu, vB);
    const unsigned ltm = (1u << lane) - 1u;
    const int cntA = __popc(bA);
    float4* wseg = s_cseg + warp * NN;
    if (vA) {
        int p = __popc(bA & ltm);
        wseg[p] = make_float4(tA.x, tA.y, (tA.y - tA.x) * cl, (float)labA);
    }
    if (vB) {
        int p = cntA + __popc(bBv & ltm);
        wseg[p] = make_float4(tB.x, tB.y, (tB.y - tB.x) * cl, (float)labB);
    }
    const int m = cntA + __popc(bBv);    // uniform across warp

    __syncwarp();                        // staging STS + compaction STS visible

    // ---- argmin over m candidates, both rows ----
    float bestA = maxn, bestB = maxn;
    int bnA = 0, bnB = 0;
    #pragma unroll 4
    for (int n = 0; n < m; n++) {
        float4 sg = wseg[n];
        bool okA = (cenA >= sg.x) && (cenA <= sg.y);
        bool okB = (cenB >= sg.x) && (cenB <= sg.y);
        float cAv = okA ? sg.z : maxn;
        float cBv = okB ? sg.z : maxn;
        if (cAv < bestA) { bestA = cAv; bnA = n; }
        if (cBv < bestB) { bestB = cBv; bnB = n; }
    }

    int confA = 0, confB = 0;
    float ll = 0.0f;
    if (m > 0) {
        const float4 bsA = wseg[bnA];
        const float4 bsB = wseg[bnB];
        confA = (bestA >= maxn) ? 0 : __float2int_rn(bsA.w);
        confB = (bestB >= maxn) ? 0 : __float2int_rn(bsB.w);
        if (confA > 0) {
            float tl = (cenA - bsA.x) * cl;
            float tr = (bsA.y - cenA) * cl;
            float inter = fminf(pA.x, tl) + fminf(pA.y, tr);
            float uni = (pA.x + pA.y) + (tl + tr) - inter;
            float ious = __fdividef(inter, fmaxf(uni, EPSF));
            float ac = fmaxf(pA.x, tl) + fmaxf(pA.y, tr);
            ll += 1.0f - (ious - __fdividef(ac - uni, fmaxf(ac, EPSF)));
        }
        if (confB > 0) {
            float tl = (cenB - bsB.x) * cl;
            float tr = (bsB.y - cenB) * cl;
            float inter = fminf(pB.x, tl) + fminf(pB.y, tr);
            float uni = (pB.x + pB.y) + (tl + tr) - inter;
            float ious = __fdividef(inter, fmaxf(uni, EPSF));
            float ac = fmaxf(pB.x, tl) + fmaxf(pB.y, tr);
            ll += 1.0f - (ious - __fdividef(ac - uni, fmaxf(ac, EPSF)));
        }
    }
    const int posflag = (confA > 0) + (confB > 0);

    // ---- focal loss: two interleaved softmax sums + target gather ----
    const float* crowA = s_conf + lrowA * CC;
    const float* crowB = s_conf + (lrowA + 32) * CC;
    float sumA = 0.0f, sumB = 0.0f;
    #pragma unroll
    for (int c = 0; c < CC; c++) {
        sumA += __expf(crowA[c]);
        sumB += __expf(crowB[c]);
    }
    float etA = __expf(crowA[confA]);
    float etB = __expf(crowB[confB]);
    float ptA = __fdividef(etA, sumA) + 1e-6f;
    float ptB = __fdividef(etB, sumB) + 1e-6f;
    float aA = (confA == 0) ? 0.25f : 0.75f;
    float aB = (confB == 0) ? 0.25f : 0.75f;
    float omA = 1.0f - ptA;
    float omB = 1.0f - ptB;
    float lc = -omA * omA * aA * __logf(ptA) - omB * omB * aB * __logf(ptB);

    // ---- block reduction (only block-wide sync in the kernel) ----
    float v0 = ll, v1 = lc;
    int vp = posflag;
    #pragma unroll
    for (int o = 16; o > 0; o >>= 1) {
        v0 += __shfl_down_sync(0xffffffffu, v0, o);
        v1 += __shfl_down_sync(0xffffffffu, v1, o);
        vp += __shfl_down_sync(0xffffffffu, vp, o);
    }
    if (lane == 0) {
        s_red_l[warp] = v0;
        s_red_c[warp] = v1;
        s_red_p[warp] = vp;
    }
    __syncthreads();
    if (tid == 0) {
        float r0 = 0.0f, r1 = 0.0f;
        int rp = 0;
        #pragma unroll
        for (int w = 0; w < NW; w++) { r0 += s_red_l[w]; r1 += s_red_c[w]; rp += s_red_p[w]; }
        g_pl[blockIdx.x] = r0;
        g_pc[blockIdx.x] = r1;
        g_pp[blockIdx.x] = rp;
        __threadfence();
        unsigned int old = atomicInc(&g_ticket, GRID - 1);  // wraps: replay-safe
        s_islast = (old == GRID - 1);
    }
    __syncthreads();

    // ---- last block: final reduction over all partials ----
    if (s_islast) {
        float f0 = 0.0f, f1 = 0.0f;
        int fp = 0;
        #pragma unroll
        for (int i = tid; i < GRID; i += RPB) {
            f0 += *(volatile float*)&g_pl[i];
            f1 += *(volatile float*)&g_pc[i];
            fp += *(volatile int*)&g_pp[i];
        }
        #pragma unroll
        for (int o = 16; o > 0; o >>= 1) {
            f0 += __shfl_down_sync(0xffffffffu, f0, o);
            f1 += __shfl_down_sync(0xffffffffu, f1, o);
            fp += __shfl_down_sync(0xffffffffu, fp, o);
        }
        if (lane == 0) {
            s_red_l[warp] = f0;
            s_red_c[warp] = f1;
            s_red_p[warp] = fp;
        }
        __syncthreads();
        if (tid == 0) {
            float r0 = 0.0f, r1 = 0.0f;
            int rp = 0;
            #pragma unroll
            for (int w = 0; w < NW; w++) { r0 += s_red_l[w]; r1 += s_red_c[w]; rp += s_red_p[w]; }
            float np = (rp > 0) ? (float)rp : 1.0f;
            out[0] = r0 / np;
            out[1] = r1 / np;
        }
    }
}

extern "C" void kernel_launch(void* const* d_in, const int* in_sizes, int n_in,
                              void* d_out, int out_size) {
    const float* loc_data  = (const float*)d_in[0];
    const float* conf_data = (const float*)d_in[1];
    const float* priors    = (const float*)d_in[2];
    const float* truths    = (const float*)d_in[3];
    const int*   labels    = (const int*)d_in[4];
    const int*   clip      = (n_in >= 6) ? (const int*)d_in[5] : nullptr;

    msl_kernel<<<GRID, RPB>>>(loc_data, conf_data, priors, truths, labels,
                              clip, (float*)d_out);
}